// round 3
// baseline (speedup 1.0000x reference)
#include <cuda_runtime.h>
#include <cstdint>

// Problem constants (fixed shapes per reference)
#define M_TOK   65536          // N*L = 16*4096
#define FEATD   512
#define H1D     1024
#define NAA     21
#define CRD     42             // 14*3
#define EPSF    1e-6f
#define MAXBLK  533            // 65536/128 + 21 (padded 128-token groups)

// -------- static device scratch (no runtime allocation allowed) ----------
__device__ float g_crd[(size_t)M_TOK * CRD];      // 11 MB  local coords
__device__ float g_table[NAA * H1D];              // 84 KB  embed[aa]@w1[882:]+b1
__device__ float g_h1[(size_t)M_TOK * H1D];       // 256 MB
__device__ float g_h2[(size_t)M_TOK * FEATD];     // 128 MB
__device__ int   g_mask_mode;                     // 0=int32, 1=float32, 2=byte
// sorting scratch
__device__ int   g_hist[NAA];
__device__ int   g_cnt[NAA];
__device__ int   g_base[NAA];
__device__ int   g_blk_aa[MAXBLK];
__device__ int   g_perm[MAXBLK * 128];

// ---------------------------------------------------------------------------
// Mask dtype sniffer (JAX bool -> unknown canonical on-device type).
// ---------------------------------------------------------------------------
__global__ void detect_mask_kernel(const unsigned int* __restrict__ m, int n_words)
{
    __shared__ int sawFloat, sawBig;
    int tid = threadIdx.x;
    if (tid == 0) { sawFloat = 0; sawBig = 0; }
    __syncthreads();
    for (int i = tid; i < n_words; i += blockDim.x) {
        unsigned v = m[i];
        if (v == 0x3F800000u)      sawFloat = 1;
        else if (v > 1u)           sawBig   = 1;
    }
    __syncthreads();
    if (tid == 0) g_mask_mode = sawFloat ? 1 : (sawBig ? 2 : 0);
}

__device__ __forceinline__ bool read_mask(const void* m, int mode, size_t i)
{
    if (mode == 0) return ((const int*)m)[i] != 0;
    if (mode == 1) return ((const float*)m)[i] != 0.0f;
    return ((const unsigned char*)m)[i] != 0;
}

// ---------------------------------------------------------------------------
// Counting sort of tokens by aa: init / hist / scan / scatter
// ---------------------------------------------------------------------------
__global__ void sort_init_kernel()
{
    int i = blockIdx.x * blockDim.x + threadIdx.x;
    if (i < NAA) { g_hist[i] = 0; g_cnt[i] = 0; }
    if (i < MAXBLK) g_blk_aa[i] = -1;
    if (i < MAXBLK * 128) g_perm[i] = -1;
}

__global__ void __launch_bounds__(256) hist_kernel(const int* __restrict__ aa)
{
    __shared__ int h[NAA];
    int tid = threadIdx.x;
    if (tid < NAA) h[tid] = 0;
    __syncthreads();
    int base = blockIdx.x * 1024;
    for (int j = tid; j < 1024; j += 256) atomicAdd(&h[aa[base + j]], 1);
    __syncthreads();
    if (tid < NAA) atomicAdd(&g_hist[tid], h[tid]);
}

__global__ void scan_kernel()
{
    if (threadIdx.x != 0) return;
    int cur = 0;
    for (int a = 0; a < NAA; a++) {
        g_base[a] = cur;
        int nb = (g_hist[a] + 127) >> 7;
        int b0 = cur >> 7;
        for (int b = 0; b < nb; b++) g_blk_aa[b0 + b] = a;
        cur += nb << 7;
    }
}

__global__ void __launch_bounds__(256) scatter_kernel(const int* __restrict__ aa)
{
    int i = blockIdx.x * blockDim.x + threadIdx.x;
    if (i >= M_TOK) return;
    int a = aa[i];
    int pos = g_base[a] + atomicAdd(&g_cnt[a], 1);
    g_perm[pos] = i;
}

// ---------------------------------------------------------------------------
// Frame construction: per token build (e1,e2,e3) and rotate+mask 14 atoms.
// ---------------------------------------------------------------------------
__global__ void __launch_bounds__(128) frame_kernel(
    const float* __restrict__ pos14, const void* __restrict__ maskp)
{
    __shared__ float sp[128 * CRD];
    const int tid  = threadIdx.x;
    const int base = blockIdx.x * 128;

    const size_t gbase = (size_t)base * CRD;
    #pragma unroll 4
    for (int i = tid; i < 128 * CRD; i += 128) sp[i] = pos14[gbase + i];
    __syncthreads();

    const float* p = &sp[tid * CRD];
    const int t = base + tid;

    const float cx = p[3], cy = p[4], cz = p[5];
    float v1x = p[6] - cx, v1y = p[7] - cy, v1z = p[8] - cz;
    float n1 = sqrtf(v1x*v1x + v1y*v1y + v1z*v1z) + EPSF;
    float e1x = v1x / n1, e1y = v1y / n1, e1z = v1z / n1;

    float v2x = p[0] - cx, v2y = p[1] - cy, v2z = p[2] - cz;
    float d = e1x*v2x + e1y*v2y + e1z*v2z;
    float u2x = v2x - d*e1x, u2y = v2y - d*e1y, u2z = v2z - d*e1z;
    float n2 = sqrtf(u2x*u2x + u2y*u2y + u2z*u2z) + EPSF;
    float e2x = u2x / n2, e2y = u2y / n2, e2z = u2z / n2;

    float e3x = e1y*e2z - e1z*e2y;
    float e3y = e1z*e2x - e1x*e2z;
    float e3z = e1x*e2y - e1y*e2x;

    const int mode = g_mask_mode;
    float r[CRD];
    #pragma unroll
    for (int a = 0; a < 14; a++) {
        float qx = p[a*3+0] - cx, qy = p[a*3+1] - cy, qz = p[a*3+2] - cz;
        bool mk = read_mask(maskp, mode, (size_t)t * 14 + a);
        r[a*3+0] = mk ? (e1x*qx + e1y*qy + e1z*qz) : 0.0f;
        r[a*3+1] = mk ? (e2x*qx + e2y*qy + e2z*qz) : 0.0f;
        r[a*3+2] = mk ? (e3x*qx + e3y*qy + e3z*qz) : 0.0f;
    }
    __syncthreads();
    #pragma unroll
    for (int i = 0; i < CRD; i++) sp[tid * CRD + i] = r[i];
    __syncthreads();
    #pragma unroll 4
    for (int i = tid; i < 128 * CRD; i += 128) g_crd[gbase + i] = sp[i];
}

// ---------------------------------------------------------------------------
// Precompute table[aa][j] = embed[aa] @ w1[882:1394, j] + b1[j]
// ---------------------------------------------------------------------------
__global__ void __launch_bounds__(256) embproj_kernel(
    const float* __restrict__ embed, const float* __restrict__ w1,
    const float* __restrict__ b1)
{
    __shared__ float se[FEATD];
    const int a = blockIdx.x;
    const int tid = threadIdx.x;
    for (int i = tid; i < FEATD; i += 256) se[i] = embed[a * FEATD + i];
    __syncthreads();

    const int j = tid * 4;
    float4 acc = *(const float4*)(b1 + j);
    const float* wp = w1 + (size_t)(NAA * CRD) * H1D + j;
    #pragma unroll 4
    for (int f = 0; f < FEATD; f++) {
        float e = se[f];
        float4 w = *(const float4*)(wp + (size_t)f * H1D);
        acc.x += e * w.x; acc.y += e * w.y; acc.z += e * w.z; acc.w += e * w.w;
    }
    *(float4*)(&g_table[a * H1D + j]) = acc;
}

// ---------------------------------------------------------------------------
__device__ __forceinline__ unsigned f2tf32(float x)
{
    float r;
    asm("cvt.rna.tf32.f32 %0, %1;" : "=f"(r) : "f"(x));
    return __float_as_uint(r);
}

// ---------------------------------------------------------------------------
// Layer 1 as aa-grouped tf32 GEMM.
// Block (bn, bm): bm = 128-token slot group (same aa), bn = 128-col chunk.
// h1[tok][col] = relu( crd[tok][0:42] @ w1[aa*42:aa*42+42][col] + table[aa][col] )
// ---------------------------------------------------------------------------
#define L1_KP 48   // K padded to 48 (6 mma k-steps)

__global__ void __launch_bounds__(256) layer1_gemm(const float* __restrict__ w1)
{
    extern __shared__ unsigned l1sm[];
    unsigned* s_crd = l1sm;                         // [128][52]
    unsigned* s_w   = l1sm + 128 * 52;              // [48][136]
    int*      s_tok = (int*)(l1sm + 128 * 52 + L1_KP * 136);
    float*    s_tab = (float*)(s_tok + 128);

    const int bm = blockIdx.y;
    const int a  = g_blk_aa[bm];
    if (a < 0) return;
    const int colbase = blockIdx.x * 128;

    const int tid  = threadIdx.x;
    const int wid  = tid >> 5;
    const int lane = tid & 31;
    const int gid  = lane >> 2;
    const int tig  = lane & 3;
    const int warpM = (wid >> 2) * 64;
    const int warpN = (wid & 3) * 32;

    // zero crd tile + load token ids + table chunk
    for (int i = tid; i < 128 * 52; i += 256) s_crd[i] = 0;
    if (tid < 128) {
        s_tok[tid] = g_perm[bm * 128 + tid];
        s_tab[tid] = g_table[a * H1D + colbase + tid];
    }
    __syncthreads();

    // gather crd rows (tf32), and stage w1 slice (42x128, rows 42..47 zero)
    for (int i = tid; i < 128 * CRD; i += 256) {
        int row = i / CRD, col = i - row * CRD;
        int t = s_tok[row];
        if (t >= 0) s_crd[row * 52 + col] = f2tf32(g_crd[(size_t)t * CRD + col]);
    }
    #pragma unroll
    for (int l = 0; l < 6; l++) {
        int s  = tid + l * 256;          // 0..1535
        int kr = s >> 5;                 // 0..47
        int nc = s & 31;                 // col/4
        float4 v = make_float4(0.f, 0.f, 0.f, 0.f);
        if (kr < CRD)
            v = *(const float4*)(w1 + (size_t)(a * CRD + kr) * H1D + colbase + nc * 4);
        s_w[kr * 136 + nc*4+0] = f2tf32(v.x);
        s_w[kr * 136 + nc*4+1] = f2tf32(v.y);
        s_w[kr * 136 + nc*4+2] = f2tf32(v.z);
        s_w[kr * 136 + nc*4+3] = f2tf32(v.w);
    }
    __syncthreads();

    float acc[4][4][4];
    #pragma unroll
    for (int i = 0; i < 4; i++)
        #pragma unroll
        for (int j = 0; j < 4; j++)
            #pragma unroll
            for (int c = 0; c < 4; c++) acc[i][j][c] = 0.0f;

    #pragma unroll
    for (int kt = 0; kt < L1_KP; kt += 8) {
        unsigned af[4][4], bf[4][2];
        #pragma unroll
        for (int mf = 0; mf < 4; mf++) {
            int r = warpM + mf * 16 + gid;
            af[mf][0] = s_crd[r * 52 + kt + tig];
            af[mf][1] = s_crd[(r + 8) * 52 + kt + tig];
            af[mf][2] = s_crd[r * 52 + kt + tig + 4];
            af[mf][3] = s_crd[(r + 8) * 52 + kt + tig + 4];
        }
        #pragma unroll
        for (int nf = 0; nf < 4; nf++) {
            int c = warpN + nf * 8 + gid;
            bf[nf][0] = s_w[(kt + tig) * 136 + c];
            bf[nf][1] = s_w[(kt + tig + 4) * 136 + c];
        }
        #pragma unroll
        for (int mf = 0; mf < 4; mf++)
            #pragma unroll
            for (int nf = 0; nf < 4; nf++)
                asm volatile(
                    "mma.sync.aligned.m16n8k8.row.col.f32.tf32.tf32.f32 "
                    "{%0,%1,%2,%3}, {%4,%5,%6,%7}, {%8,%9}, {%0,%1,%2,%3};"
                    : "+f"(acc[mf][nf][0]), "+f"(acc[mf][nf][1]),
                      "+f"(acc[mf][nf][2]), "+f"(acc[mf][nf][3])
                    : "r"(af[mf][0]), "r"(af[mf][1]), "r"(af[mf][2]), "r"(af[mf][3]),
                      "r"(bf[nf][0]), "r"(bf[nf][1]));
    }

    // epilogue: + table, relu, scatter-store to g_h1 rows
    #pragma unroll
    for (int nf = 0; nf < 4; nf++) {
        int c = warpN + nf * 8 + 2 * tig;
        float bx = s_tab[c], by = s_tab[c + 1];
        #pragma unroll
        for (int mf = 0; mf < 4; mf++) {
            int r = warpM + mf * 16 + gid;
            int t0 = s_tok[r], t1 = s_tok[r + 8];
            if (t0 >= 0) {
                float2 o;
                o.x = fmaxf(acc[mf][nf][0] + bx, 0.f);
                o.y = fmaxf(acc[mf][nf][1] + by, 0.f);
                *(float2*)(g_h1 + (size_t)t0 * H1D + colbase + c) = o;
            }
            if (t1 >= 0) {
                float2 o;
                o.x = fmaxf(acc[mf][nf][2] + bx, 0.f);
                o.y = fmaxf(acc[mf][nf][3] + by, 0.f);
                *(float2*)(g_h1 + (size_t)t1 * H1D + colbase + c) = o;
            }
        }
    }
}

// ---------------------------------------------------------------------------
// tf32 tensor-core GEMM, double-buffered. C = act(A[M,K] @ W[K,N] + b).
// Tile 128x128x32, 256 thr, warp tile 64x32, mma.m16n8k8.tf32.
// ---------------------------------------------------------------------------
#define GEMM_SMEM (2 * (128 * 36 + 32 * 136) * 4)

__global__ void __launch_bounds__(256) gemm_tf32(
    const float* __restrict__ A, const float* __restrict__ W,
    const float* __restrict__ bias, float* __restrict__ C,
    int M, int K, int N, int relu)
{
    extern __shared__ unsigned dsm[];
    unsigned* As = dsm;                  // [2][128][36]
    unsigned* Ws = dsm + 2 * 128 * 36;   // [2][32][136]

    const int tid  = threadIdx.x;
    const int wid  = tid >> 5;
    const int lane = tid & 31;
    const int gid  = lane >> 2;
    const int tig  = lane & 3;
    const int warpM = (wid >> 2) * 64;
    const int warpN = (wid & 3) * 32;
    const int row0 = blockIdx.y * 128;
    const int col0 = blockIdx.x * 128;

    // per-thread staging coordinates (fixed across tiles)
    const int ar = (tid * 2) >> 4;         // reuse below via s-index math
    (void)ar;

    float acc[4][4][4];
    #pragma unroll
    for (int i = 0; i < 4; i++)
        #pragma unroll
        for (int j = 0; j < 4; j++)
            #pragma unroll
            for (int c = 0; c < 4; c++) acc[i][j][c] = 0.0f;

    float4 va[4], vw[4];

    // ---- load tile k0 into registers
    #define LOAD_TILES(K0)                                                     \
        {                                                                      \
            _Pragma("unroll")                                                  \
            for (int l = 0; l < 4; l++) {                                      \
                int s  = tid + l * 256;                                        \
                int r  = s >> 3;                                               \
                int kq = s & 7;                                                \
                va[l] = *(const float4*)(A + (size_t)(row0 + r) * K + (K0) + kq * 4); \
            }                                                                  \
            _Pragma("unroll")                                                  \
            for (int l = 0; l < 4; l++) {                                      \
                int s  = tid + l * 256;                                        \
                int kr = s >> 5;                                               \
                int nc = s & 31;                                               \
                vw[l] = *(const float4*)(W + (size_t)((K0) + kr) * N + col0 + nc * 4); \
            }                                                                  \
        }

    #define STORE_TILES(BUF)                                                   \
        {                                                                      \
            _Pragma("unroll")                                                  \
            for (int l = 0; l < 4; l++) {                                      \
                int s  = tid + l * 256;                                        \
                int r  = s >> 3;                                               \
                int kq = s & 7;                                                \
                unsigned* p = &As[((BUF) * 128 + r) * 36 + kq * 4];            \
                p[0] = f2tf32(va[l].x); p[1] = f2tf32(va[l].y);                \
                p[2] = f2tf32(va[l].z); p[3] = f2tf32(va[l].w);                \
            }                                                                  \
            _Pragma("unroll")                                                  \
            for (int l = 0; l < 4; l++) {                                      \
                int s  = tid + l * 256;                                        \
                int kr = s >> 5;                                               \
                int nc = s & 31;                                               \
                unsigned* p = &Ws[((BUF) * 32 + kr) * 136 + nc * 4];           \
                p[0] = f2tf32(vw[l].x); p[1] = f2tf32(vw[l].y);                \
                p[2] = f2tf32(vw[l].z); p[3] = f2tf32(vw[l].w);                \
            }                                                                  \
        }

    const int nk = K >> 5;
    LOAD_TILES(0);
    STORE_TILES(0);
    __syncthreads();

    for (int ks = 0; ks < nk; ks++) {
        const int cur = ks & 1;
        const bool more = (ks + 1 < nk);
        if (more) LOAD_TILES((ks + 1) << 5);

        const unsigned* Ab = &As[cur * 128 * 36];
        const unsigned* Wb = &Ws[cur * 32 * 136];
        #pragma unroll
        for (int kt = 0; kt < 32; kt += 8) {
            unsigned af[4][4], bf[4][2];
            #pragma unroll
            for (int mf = 0; mf < 4; mf++) {
                int r = warpM + mf * 16 + gid;
                af[mf][0] = Ab[r * 36 + kt + tig];
                af[mf][1] = Ab[(r + 8) * 36 + kt + tig];
                af[mf][2] = Ab[r * 36 + kt + tig + 4];
                af[mf][3] = Ab[(r + 8) * 36 + kt + tig + 4];
            }
            #pragma unroll
            for (int nf = 0; nf < 4; nf++) {
                int c = warpN + nf * 8 + gid;
                bf[nf][0] = Wb[(kt + tig) * 136 + c];
                bf[nf][1] = Wb[(kt + tig + 4) * 136 + c];
            }
            #pragma unroll
            for (int mf = 0; mf < 4; mf++)
                #pragma unroll
                for (int nf = 0; nf < 4; nf++)
                    asm volatile(
                        "mma.sync.aligned.m16n8k8.row.col.f32.tf32.tf32.f32 "
                        "{%0,%1,%2,%3}, {%4,%5,%6,%7}, {%8,%9}, {%0,%1,%2,%3};"
                        : "+f"(acc[mf][nf][0]), "+f"(acc[mf][nf][1]),
                          "+f"(acc[mf][nf][2]), "+f"(acc[mf][nf][3])
                        : "r"(af[mf][0]), "r"(af[mf][1]), "r"(af[mf][2]), "r"(af[mf][3]),
                          "r"(bf[nf][0]), "r"(bf[nf][1]));
        }
        if (more) STORE_TILES(1 - cur);
        __syncthreads();
    }

    // epilogue: bias + optional relu
    #pragma unroll
    for (int nf = 0; nf < 4; nf++) {
        int c = col0 + warpN + nf * 8 + 2 * tig;
        float bx = bias[c], by = bias[c + 1];
        #pragma unroll
        for (int mf = 0; mf < 4; mf++) {
            int r = row0 + warpM + mf * 16 + gid;
            float2 o0, o1;
            o0.x = acc[mf][nf][0] + bx; o0.y = acc[mf][nf][1] + by;
            o1.x = acc[mf][nf][2] + bx; o1.y = acc[mf][nf][3] + by;
            if (relu) {
                o0.x = fmaxf(o0.x, 0.f); o0.y = fmaxf(o0.y, 0.f);
                o1.x = fmaxf(o1.x, 0.f); o1.y = fmaxf(o1.y, 0.f);
            }
            *(float2*)(C + (size_t)r * N + c)       = o0;
            *(float2*)(C + (size_t)(r + 8) * N + c) = o1;
        }
    }
}

extern "C" void kernel_launch(void* const* d_in, const int* in_sizes, int n_in,
                              void* d_out, int out_size)
{
    const int*   aa    = (const int*)  d_in[0];
    const float* pos14 = (const float*)d_in[1];
    const void*  amask =               d_in[2];
    const float* embed = (const float*)d_in[3];
    const float* w1    = (const float*)d_in[4];
    const float* b1    = (const float*)d_in[5];
    const float* w2    = (const float*)d_in[6];
    const float* b2    = (const float*)d_in[7];
    const float* w3    = (const float*)d_in[8];
    const float* b3    = (const float*)d_in[9];
    const float* w4    = (const float*)d_in[10];
    const float* b4    = (const float*)d_in[11];
    float* out = (float*)d_out;

    float *p_h1, *p_h2;
    cudaGetSymbolAddress((void**)&p_h1, g_h1);
    cudaGetSymbolAddress((void**)&p_h2, g_h2);

    static int attr_done = 0;
    if (!attr_done) {
        cudaFuncSetAttribute(gemm_tf32, cudaFuncAttributeMaxDynamicSharedMemorySize,
                             GEMM_SMEM);
        int l1sm = (128 * 52 + L1_KP * 136) * 4 + 128 * 4 + 128 * 4;
        cudaFuncSetAttribute(layer1_gemm, cudaFuncAttributeMaxDynamicSharedMemorySize,
                             l1sm);
        attr_done = 1;
    }

    // sort tokens by aa
    sort_init_kernel<<<(MAXBLK * 128 + 255) / 256, 256>>>();
    hist_kernel<<<M_TOK / 1024, 256>>>(aa);
    scan_kernel<<<1, 32>>>();
    scatter_kernel<<<M_TOK / 256, 256>>>(aa);

    // geometry + aa-table
    detect_mask_kernel<<<1, 256>>>((const unsigned int*)amask, 4096);
    frame_kernel<<<M_TOK / 128, 128>>>(pos14, amask);
    embproj_kernel<<<NAA, 256>>>(embed, w1, b1);

    // layer 1 (grouped tf32 GEMM)
    {
        int l1sm = (128 * 52 + L1_KP * 136) * 4 + 128 * 4 + 128 * 4;
        dim3 g(H1D / 128, MAXBLK);     // (8, 533)
        layer1_gemm<<<g, 256, l1sm>>>(w1);
    }

    // dense MLP (double-buffered tf32)
    {
        dim3 blk(256);
        dim3 g2(FEATD / 128, M_TOK / 128);   // (4, 512)
        gemm_tf32<<<g2, blk, GEMM_SMEM>>>(p_h1, w2, b2, p_h2, M_TOK, H1D,  FEATD, 1);
        gemm_tf32<<<g2, blk, GEMM_SMEM>>>(p_h2, w3, b3, p_h1, M_TOK, FEATD, FEATD, 1);
        gemm_tf32<<<g2, blk, GEMM_SMEM>>>(p_h1, w4, b4, out,  M_TOK, FEATD, FEATD, 0);
    }
}

// round 5
// speedup vs baseline: 1.3594x; 1.3594x over previous
#include <cuda_runtime.h>
#include <cuda_fp16.h>
#include <cstdint>

// Problem constants (fixed shapes per reference)
#define M_TOK   65536          // N*L = 16*4096
#define FEATD   512
#define H1D     1024
#define NAA     21
#define CRD     42             // 14*3
#define EPSF    1e-6f
#define MAXBLK  533            // 65536/128 + 21 (padded 128-token groups)

// -------- static device scratch (no runtime allocation allowed) ----------
__device__ float g_crd[(size_t)M_TOK * CRD];      // 11 MB  local coords
__device__ float g_table[NAA * H1D];              // 84 KB  embed[aa]@w1[882:]+b1
__device__ float g_h1[(size_t)M_TOK * H1D];       // 256 MB
__device__ float g_h2[(size_t)M_TOK * FEATD];     // 128 MB
__device__ int   g_mask_mode;                     // 0=int32, 1=float32, 2=byte
// sorting scratch
__device__ int   g_hist[NAA];
__device__ int   g_cnt[NAA];
__device__ int   g_base[NAA];
__device__ int   g_blk_aa[MAXBLK];
__device__ int   g_perm[MAXBLK * 128];

// ---------------------------------------------------------------------------
// Mask dtype sniffer (JAX bool -> unknown canonical on-device type).
// ---------------------------------------------------------------------------
__global__ void detect_mask_kernel(const unsigned int* __restrict__ m, int n_words)
{
    __shared__ int sawFloat, sawBig;
    int tid = threadIdx.x;
    if (tid == 0) { sawFloat = 0; sawBig = 0; }
    __syncthreads();
    for (int i = tid; i < n_words; i += blockDim.x) {
        unsigned v = m[i];
        if (v == 0x3F800000u)      sawFloat = 1;
        else if (v > 1u)           sawBig   = 1;
    }
    __syncthreads();
    if (tid == 0) g_mask_mode = sawFloat ? 1 : (sawBig ? 2 : 0);
}

__device__ __forceinline__ bool read_mask(const void* m, int mode, size_t i)
{
    if (mode == 0) return ((const int*)m)[i] != 0;
    if (mode == 1) return ((const float*)m)[i] != 0.0f;
    return ((const unsigned char*)m)[i] != 0;
}

// ---------------------------------------------------------------------------
// Counting sort of tokens by aa
// ---------------------------------------------------------------------------
__global__ void sort_init_kernel()
{
    int i = blockIdx.x * blockDim.x + threadIdx.x;
    if (i < NAA) { g_hist[i] = 0; g_cnt[i] = 0; }
    if (i < MAXBLK) g_blk_aa[i] = -1;
    if (i < MAXBLK * 128) g_perm[i] = -1;
}

__global__ void __launch_bounds__(256) hist_kernel(const int* __restrict__ aa)
{
    __shared__ int h[NAA];
    int tid = threadIdx.x;
    if (tid < NAA) h[tid] = 0;
    __syncthreads();
    int base = blockIdx.x * 1024;
    for (int j = tid; j < 1024; j += 256) atomicAdd(&h[aa[base + j]], 1);
    __syncthreads();
    if (tid < NAA) atomicAdd(&g_hist[tid], h[tid]);
}

__global__ void scan_kernel()
{
    if (threadIdx.x != 0) return;
    int cur = 0;
    for (int a = 0; a < NAA; a++) {
        g_base[a] = cur;
        int nb = (g_hist[a] + 127) >> 7;
        int b0 = cur >> 7;
        for (int b = 0; b < nb; b++) g_blk_aa[b0 + b] = a;
        cur += nb << 7;
    }
}

__global__ void __launch_bounds__(256) scatter_kernel(const int* __restrict__ aa)
{
    int i = blockIdx.x * blockDim.x + threadIdx.x;
    if (i >= M_TOK) return;
    int a = aa[i];
    int pos = g_base[a] + atomicAdd(&g_cnt[a], 1);
    g_perm[pos] = i;
}

// ---------------------------------------------------------------------------
// Frame construction
// ---------------------------------------------------------------------------
__global__ void __launch_bounds__(128) frame_kernel(
    const float* __restrict__ pos14, const void* __restrict__ maskp)
{
    __shared__ float sp[128 * CRD];
    const int tid  = threadIdx.x;
    const int base = blockIdx.x * 128;

    const size_t gbase = (size_t)base * CRD;
    #pragma unroll 4
    for (int i = tid; i < 128 * CRD; i += 128) sp[i] = pos14[gbase + i];
    __syncthreads();

    const float* p = &sp[tid * CRD];
    const int t = base + tid;

    const float cx = p[3], cy = p[4], cz = p[5];
    float v1x = p[6] - cx, v1y = p[7] - cy, v1z = p[8] - cz;
    float n1 = sqrtf(v1x*v1x + v1y*v1y + v1z*v1z) + EPSF;
    float e1x = v1x / n1, e1y = v1y / n1, e1z = v1z / n1;

    float v2x = p[0] - cx, v2y = p[1] - cy, v2z = p[2] - cz;
    float d = e1x*v2x + e1y*v2y + e1z*v2z;
    float u2x = v2x - d*e1x, u2y = v2y - d*e1y, u2z = v2z - d*e1z;
    float n2 = sqrtf(u2x*u2x + u2y*u2y + u2z*u2z) + EPSF;
    float e2x = u2x / n2, e2y = u2y / n2, e2z = u2z / n2;

    float e3x = e1y*e2z - e1z*e2y;
    float e3y = e1z*e2x - e1x*e2z;
    float e3z = e1x*e2y - e1y*e2x;

    const int mode = g_mask_mode;
    float r[CRD];
    #pragma unroll
    for (int a = 0; a < 14; a++) {
        float qx = p[a*3+0] - cx, qy = p[a*3+1] - cy, qz = p[a*3+2] - cz;
        bool mk = read_mask(maskp, mode, (size_t)t * 14 + a);
        r[a*3+0] = mk ? (e1x*qx + e1y*qy + e1z*qz) : 0.0f;
        r[a*3+1] = mk ? (e2x*qx + e2y*qy + e2z*qz) : 0.0f;
        r[a*3+2] = mk ? (e3x*qx + e3y*qy + e3z*qz) : 0.0f;
    }
    __syncthreads();
    #pragma unroll
    for (int i = 0; i < CRD; i++) sp[tid * CRD + i] = r[i];
    __syncthreads();
    #pragma unroll 4
    for (int i = tid; i < 128 * CRD; i += 128) g_crd[gbase + i] = sp[i];
}

// ---------------------------------------------------------------------------
// table[aa][j] = embed[aa] @ w1[882:1394, j] + b1[j]
// ---------------------------------------------------------------------------
__global__ void __launch_bounds__(256) embproj_kernel(
    const float* __restrict__ embed, const float* __restrict__ w1,
    const float* __restrict__ b1)
{
    __shared__ float se[FEATD];
    const int a = blockIdx.x;
    const int tid = threadIdx.x;
    for (int i = tid; i < FEATD; i += 256) se[i] = embed[a * FEATD + i];
    __syncthreads();

    const int j = tid * 4;
    float4 acc = *(const float4*)(b1 + j);
    const float* wp = w1 + (size_t)(NAA * CRD) * H1D + j;
    #pragma unroll 4
    for (int f = 0; f < FEATD; f++) {
        float e = se[f];
        float4 w = *(const float4*)(wp + (size_t)f * H1D);
        acc.x += e * w.x; acc.y += e * w.y; acc.z += e * w.z; acc.w += e * w.w;
    }
    *(float4*)(&g_table[a * H1D + j]) = acc;
}

// ---------------------------------------------------------------------------
__device__ __forceinline__ unsigned f2tf32(float x)
{
    float r;
    asm("cvt.rna.tf32.f32 %0, %1;" : "=f"(r) : "f"(x));
    return __float_as_uint(r);
}

__device__ __forceinline__ unsigned pack_h2(float a, float b)
{
    __half2 h = __floats2half2_rn(a, b);
    return *(unsigned*)&h;
}

// ---------------------------------------------------------------------------
// Layer 1 as aa-grouped tf32 mma.sync GEMM (K=42 padded to 48)
// ---------------------------------------------------------------------------
#define L1_KP 48

__global__ void __launch_bounds__(256) layer1_gemm(const float* __restrict__ w1)
{
    extern __shared__ unsigned l1sm[];
    unsigned* s_crd = l1sm;                         // [128][52]
    unsigned* s_w   = l1sm + 128 * 52;              // [48][136]
    int*      s_tok = (int*)(l1sm + 128 * 52 + L1_KP * 136);
    float*    s_tab = (float*)(s_tok + 128);

    const int bm = blockIdx.y;
    const int a  = g_blk_aa[bm];
    if (a < 0) return;
    const int colbase = blockIdx.x * 128;

    const int tid  = threadIdx.x;
    const int wid  = tid >> 5;
    const int lane = tid & 31;
    const int gid  = lane >> 2;
    const int tig  = lane & 3;
    const int warpM = (wid >> 2) * 64;
    const int warpN = (wid & 3) * 32;

    for (int i = tid; i < 128 * 52; i += 256) s_crd[i] = 0;
    if (tid < 128) {
        s_tok[tid] = g_perm[bm * 128 + tid];
        s_tab[tid] = g_table[a * H1D + colbase + tid];
    }
    __syncthreads();

    for (int i = tid; i < 128 * CRD; i += 256) {
        int row = i / CRD, col = i - row * CRD;
        int t = s_tok[row];
        if (t >= 0) s_crd[row * 52 + col] = f2tf32(g_crd[(size_t)t * CRD + col]);
    }
    #pragma unroll
    for (int l = 0; l < 6; l++) {
        int s  = tid + l * 256;
        int kr = s >> 5;
        int nc = s & 31;
        float4 v = make_float4(0.f, 0.f, 0.f, 0.f);
        if (kr < CRD)
            v = *(const float4*)(w1 + (size_t)(a * CRD + kr) * H1D + colbase + nc * 4);
        s_w[kr * 136 + nc*4+0] = f2tf32(v.x);
        s_w[kr * 136 + nc*4+1] = f2tf32(v.y);
        s_w[kr * 136 + nc*4+2] = f2tf32(v.z);
        s_w[kr * 136 + nc*4+3] = f2tf32(v.w);
    }
    __syncthreads();

    float acc[4][4][4];
    #pragma unroll
    for (int i = 0; i < 4; i++)
        #pragma unroll
        for (int j = 0; j < 4; j++)
            #pragma unroll
            for (int c = 0; c < 4; c++) acc[i][j][c] = 0.0f;

    #pragma unroll
    for (int kt = 0; kt < L1_KP; kt += 8) {
        unsigned af[4][4], bf[4][2];
        #pragma unroll
        for (int mf = 0; mf < 4; mf++) {
            int r = warpM + mf * 16 + gid;
            af[mf][0] = s_crd[r * 52 + kt + tig];
            af[mf][1] = s_crd[(r + 8) * 52 + kt + tig];
            af[mf][2] = s_crd[r * 52 + kt + tig + 4];
            af[mf][3] = s_crd[(r + 8) * 52 + kt + tig + 4];
        }
        #pragma unroll
        for (int nf = 0; nf < 4; nf++) {
            int c = warpN + nf * 8 + gid;
            bf[nf][0] = s_w[(kt + tig) * 136 + c];
            bf[nf][1] = s_w[(kt + tig + 4) * 136 + c];
        }
        #pragma unroll
        for (int mf = 0; mf < 4; mf++)
            #pragma unroll
            for (int nf = 0; nf < 4; nf++)
                asm volatile(
                    "mma.sync.aligned.m16n8k8.row.col.f32.tf32.tf32.f32 "
                    "{%0,%1,%2,%3}, {%4,%5,%6,%7}, {%8,%9}, {%0,%1,%2,%3};"
                    : "+f"(acc[mf][nf][0]), "+f"(acc[mf][nf][1]),
                      "+f"(acc[mf][nf][2]), "+f"(acc[mf][nf][3])
                    : "r"(af[mf][0]), "r"(af[mf][1]), "r"(af[mf][2]), "r"(af[mf][3]),
                      "r"(bf[nf][0]), "r"(bf[nf][1]));
    }

    #pragma unroll
    for (int nf = 0; nf < 4; nf++) {
        int c = warpN + nf * 8 + 2 * tig;
        float bx = s_tab[c], by = s_tab[c + 1];
        #pragma unroll
        for (int mf = 0; mf < 4; mf++) {
            int r = warpM + mf * 16 + gid;
            int t0 = s_tok[r], t1 = s_tok[r + 8];
            if (t0 >= 0) {
                float2 o;
                o.x = fmaxf(acc[mf][nf][0] + bx, 0.f);
                o.y = fmaxf(acc[mf][nf][1] + by, 0.f);
                *(float2*)(g_h1 + (size_t)t0 * H1D + colbase + c) = o;
            }
            if (t1 >= 0) {
                float2 o;
                o.x = fmaxf(acc[mf][nf][2] + bx, 0.f);
                o.y = fmaxf(acc[mf][nf][3] + by, 0.f);
                *(float2*)(g_h1 + (size_t)t1 * H1D + colbase + c) = o;
            }
        }
    }
}

// ---------------------------------------------------------------------------
// fp16 tensor-core GEMM with fused bias + optional ReLU (fp32 accumulate).
// C[M,N] = act(A[M,K] @ W[K,N] + b).  Tile 128x128x32, 256 thr (8 warps),
// warp tile 64x32, mma.sync.m16n8k16.f16 (fp32 acc).  M%128, N%128, K%32 == 0.
// Half2 packing: A pairs along k -> Ah[row][k/2]; W pairs along k -> Wh[k/2][n].
// ---------------------------------------------------------------------------
__global__ void __launch_bounds__(256) gemm_f16(
    const float* __restrict__ A, const float* __restrict__ W,
    const float* __restrict__ bias, float* __restrict__ C,
    int M, int K, int N, int relu)
{
    __shared__ unsigned Ah[128][20];    // [m][k2], pad 4
    __shared__ unsigned Wh[16][136];    // [k2][n], pad 8

    const int tid  = threadIdx.x;
    const int wid  = tid >> 5;
    const int lane = tid & 31;
    const int gid  = lane >> 2;         // 0..7
    const int tig  = lane & 3;          // 0..3
    const int warpM = (wid >> 2) * 64;  // 0 or 64
    const int warpN = (wid & 3) * 32;   // 0,32,64,96
    const int row0 = blockIdx.y * 128;
    const int col0 = blockIdx.x * 128;

    float acc[4][4][4];
    #pragma unroll
    for (int i = 0; i < 4; i++)
        #pragma unroll
        for (int j = 0; j < 4; j++)
            #pragma unroll
            for (int c = 0; c < 4; c++) acc[i][j][c] = 0.0f;

    for (int k0 = 0; k0 < K; k0 += 32) {
        // stage A tile 128x32 floats -> Ah[128][16] half2 (512 uint4, 2/thread)
        #pragma unroll
        for (int l = 0; l < 2; l++) {
            int s  = tid + l * 256;         // 0..511
            int r  = s >> 2;                // 0..127
            int kq = s & 3;                 // 0..3 (8 floats each)
            const float* ap = A + (size_t)(row0 + r) * K + k0 + kq * 8;
            float4 v0 = *(const float4*)(ap);
            float4 v1 = *(const float4*)(ap + 4);
            uint4 t;
            t.x = pack_h2(v0.x, v0.y); t.y = pack_h2(v0.z, v0.w);
            t.z = pack_h2(v1.x, v1.y); t.w = pack_h2(v1.z, v1.w);
            *(uint4*)&Ah[r][kq * 4] = t;
        }
        // stage W tile 32x128 floats -> Wh[16][128] half2 pairs-along-k
        #pragma unroll
        for (int l = 0; l < 2; l++) {
            int s  = tid + l * 256;         // 0..511
            int kr = s >> 5;                // 0..15 (k2 index)
            int nc = s & 31;                // col/4
            const float* wp = W + (size_t)(k0 + 2 * kr) * N + col0 + nc * 4;
            float4 v0 = *(const float4*)(wp);        // k even
            float4 v1 = *(const float4*)(wp + N);    // k odd
            uint4 t;
            t.x = pack_h2(v0.x, v1.x); t.y = pack_h2(v0.y, v1.y);
            t.z = pack_h2(v0.z, v1.z); t.w = pack_h2(v0.w, v1.w);
            *(uint4*)&Wh[kr][nc * 4] = t;
        }
        __syncthreads();

        #pragma unroll
        for (int kt = 0; kt < 2; kt++) {        // two k16 steps per chunk
            const int kb = kt * 8;              // k2 base
            unsigned af[4][4], bf[4][2];
            #pragma unroll
            for (int mf = 0; mf < 4; mf++) {
                int r = warpM + mf * 16 + gid;
                af[mf][0] = Ah[r    ][kb + tig];
                af[mf][1] = Ah[r + 8][kb + tig];
                af[mf][2] = Ah[r    ][kb + tig + 4];
                af[mf][3] = Ah[r + 8][kb + tig + 4];
            }
            #pragma unroll
            for (int nf = 0; nf < 4; nf++) {
                int c = warpN + nf * 8 + gid;
                bf[nf][0] = Wh[kb + tig    ][c];
                bf[nf][1] = Wh[kb + tig + 4][c];
            }
            #pragma unroll
            for (int mf = 0; mf < 4; mf++)
                #pragma unroll
                for (int nf = 0; nf < 4; nf++)
                    asm volatile(
                        "mma.sync.aligned.m16n8k16.row.col.f32.f16.f16.f32 "
                        "{%0,%1,%2,%3}, {%4,%5,%6,%7}, {%8,%9}, {%0,%1,%2,%3};"
                        : "+f"(acc[mf][nf][0]), "+f"(acc[mf][nf][1]),
                          "+f"(acc[mf][nf][2]), "+f"(acc[mf][nf][3])
                        : "r"(af[mf][0]), "r"(af[mf][1]), "r"(af[mf][2]), "r"(af[mf][3]),
                          "r"(bf[nf][0]), "r"(bf[nf][1]));
        }
        __syncthreads();
    }

    // epilogue: bias + optional relu, float2 stores (adjacent cols per c-pair)
    #pragma unroll
    for (int nf = 0; nf < 4; nf++) {
        int c = col0 + warpN + nf * 8 + 2 * tig;
        float bx = bias[c], by = bias[c + 1];
        #pragma unroll
        for (int mf = 0; mf < 4; mf++) {
            int r = row0 + warpM + mf * 16 + gid;
            float2 o0, o1;
            o0.x = acc[mf][nf][0] + bx; o0.y = acc[mf][nf][1] + by;
            o1.x = acc[mf][nf][2] + bx; o1.y = acc[mf][nf][3] + by;
            if (relu) {
                o0.x = fmaxf(o0.x, 0.f); o0.y = fmaxf(o0.y, 0.f);
                o1.x = fmaxf(o1.x, 0.f); o1.y = fmaxf(o1.y, 0.f);
            }
            *(float2*)(C + (size_t)r * N + c)       = o0;
            *(float2*)(C + (size_t)(r + 8) * N + c) = o1;
        }
    }
}

extern "C" void kernel_launch(void* const* d_in, const int* in_sizes, int n_in,
                              void* d_out, int out_size)
{
    const int*   aa    = (const int*)  d_in[0];
    const float* pos14 = (const float*)d_in[1];
    const void*  amask =               d_in[2];
    const float* embed = (const float*)d_in[3];
    const float* w1    = (const float*)d_in[4];
    const float* b1    = (const float*)d_in[5];
    const float* w2    = (const float*)d_in[6];
    const float* b2    = (const float*)d_in[7];
    const float* w3    = (const float*)d_in[8];
    const float* b3    = (const float*)d_in[9];
    const float* w4    = (const float*)d_in[10];
    const float* b4    = (const float*)d_in[11];
    float* out = (float*)d_out;

    float *p_h1, *p_h2;
    cudaGetSymbolAddress((void**)&p_h1, g_h1);
    cudaGetSymbolAddress((void**)&p_h2, g_h2);

    const int l1sm = (128 * 52 + L1_KP * 136) * 4 + 128 * 4 + 128 * 4;
    cudaFuncSetAttribute(layer1_gemm, cudaFuncAttributeMaxDynamicSharedMemorySize,
                         l1sm);

    // sort tokens by aa
    sort_init_kernel<<<(MAXBLK * 128 + 255) / 256, 256>>>();
    hist_kernel<<<M_TOK / 1024, 256>>>(aa);
    scan_kernel<<<1, 32>>>();
    scatter_kernel<<<M_TOK / 256, 256>>>(aa);

    // geometry + aa-table
    detect_mask_kernel<<<1, 256>>>((const unsigned int*)amask, 4096);
    frame_kernel<<<M_TOK / 128, 128>>>(pos14, amask);
    embproj_kernel<<<NAA, 256>>>(embed, w1, b1);

    // layer 1 (grouped tf32 GEMM)
    {
        dim3 g(H1D / 128, MAXBLK);
        layer1_gemm<<<g, 256, l1sm>>>(w1);
    }

    // dense MLP (fp16 mma, fp32 accumulate)
    {
        dim3 blk(256);
        dim3 g2(FEATD / 128, M_TOK / 128);   // (4, 512)
        gemm_f16<<<g2, blk>>>(p_h1, w2, b2, p_h2, M_TOK, H1D,  FEATD, 1);
        gemm_f16<<<g2, blk>>>(p_h2, w3, b3, p_h1, M_TOK, FEATD, FEATD, 1);
        gemm_f16<<<g2, blk>>>(p_h1, w4, b4, out,  M_TOK, FEATD, FEATD, 0);
    }
}

// round 6
// speedup vs baseline: 1.7792x; 1.3088x over previous
#include <cuda_runtime.h>
#include <cuda_fp16.h>
#include <cstdint>

// Problem constants (fixed shapes per reference)
#define M_TOK   65536          // N*L = 16*4096
#define FEATD   512
#define H1D     1024
#define NAA     21
#define CRD     42             // 14*3
#define EPSF    1e-6f
#define MAXBLK  533            // 65536/128 + 21 (padded 128-token groups)

// -------- static device scratch (no runtime allocation allowed) ----------
__device__ float    g_crd[(size_t)M_TOK * CRD];        // local coords
__device__ float    g_table[NAA * H1D];                // embed[aa]@w1[882:]+b1
__device__ __half   g_h1h[(size_t)M_TOK * H1D];        // 128 MB  (fp16 h1)
__device__ __half   g_h2h[(size_t)M_TOK * FEATD];      // 64 MB   (fp16 h2/h3)
__device__ __half   g_h3h[(size_t)M_TOK * FEATD];      // 64 MB
__device__ unsigned g_w2p[(size_t)(H1D/2)  * FEATD];   // k-pair packed half2
__device__ unsigned g_w3p[(size_t)(FEATD/2)* FEATD];
__device__ unsigned g_w4p[(size_t)(FEATD/2)* FEATD];
__device__ int      g_mask_mode;
// sorting scratch
__device__ int   g_hist[NAA];
__device__ int   g_cnt[NAA];
__device__ int   g_base[NAA];
__device__ int   g_blk_aa[MAXBLK];
__device__ int   g_perm[MAXBLK * 128];

// ---------------------------------------------------------------------------
__device__ __forceinline__ uint32_t smem_u32(const void* p)
{
    uint32_t a;
    asm("{ .reg .u64 t; cvta.to.shared.u64 t, %1; cvt.u32.u64 %0, t; }"
        : "=r"(a) : "l"(p));
    return a;
}

#define CP_ASYNC16(dst, src) \
    asm volatile("cp.async.cg.shared.global [%0], [%1], 16;" \
                 :: "r"(dst), "l"(src) : "memory")
#define CP_COMMIT()  asm volatile("cp.async.commit_group;" ::: "memory")
#define CP_WAIT(n)   asm volatile("cp.async.wait_group %0;" :: "n"(n) : "memory")

__device__ __forceinline__ unsigned f2tf32(float x)
{
    float r;
    asm("cvt.rna.tf32.f32 %0, %1;" : "=f"(r) : "f"(x));
    return __float_as_uint(r);
}

__device__ __forceinline__ unsigned pack_h2(float a, float b)
{
    __half2 h = __floats2half2_rn(a, b);
    return *(unsigned*)&h;
}

// ---------------------------------------------------------------------------
// Mask dtype sniffer
// ---------------------------------------------------------------------------
__global__ void detect_mask_kernel(const unsigned int* __restrict__ m, int n_words)
{
    __shared__ int sawFloat, sawBig;
    int tid = threadIdx.x;
    if (tid == 0) { sawFloat = 0; sawBig = 0; }
    __syncthreads();
    for (int i = tid; i < n_words; i += blockDim.x) {
        unsigned v = m[i];
        if (v == 0x3F800000u)      sawFloat = 1;
        else if (v > 1u)           sawBig   = 1;
    }
    __syncthreads();
    if (tid == 0) g_mask_mode = sawFloat ? 1 : (sawBig ? 2 : 0);
}

__device__ __forceinline__ bool read_mask(const void* m, int mode, size_t i)
{
    if (mode == 0) return ((const int*)m)[i] != 0;
    if (mode == 1) return ((const float*)m)[i] != 0.0f;
    return ((const unsigned char*)m)[i] != 0;
}

// ---------------------------------------------------------------------------
// Counting sort of tokens by aa
// ---------------------------------------------------------------------------
__global__ void sort_init_kernel()
{
    int i = blockIdx.x * blockDim.x + threadIdx.x;
    if (i < NAA) { g_hist[i] = 0; g_cnt[i] = 0; }
    if (i < MAXBLK) g_blk_aa[i] = -1;
    if (i < MAXBLK * 128) g_perm[i] = -1;
}

__global__ void __launch_bounds__(256) hist_kernel(const int* __restrict__ aa)
{
    __shared__ int h[NAA];
    int tid = threadIdx.x;
    if (tid < NAA) h[tid] = 0;
    __syncthreads();
    int base = blockIdx.x * 1024;
    for (int j = tid; j < 1024; j += 256) atomicAdd(&h[aa[base + j]], 1);
    __syncthreads();
    if (tid < NAA) atomicAdd(&g_hist[tid], h[tid]);
}

__global__ void scan_kernel()
{
    if (threadIdx.x != 0) return;
    int cur = 0;
    for (int a = 0; a < NAA; a++) {
        g_base[a] = cur;
        int nb = (g_hist[a] + 127) >> 7;
        int b0 = cur >> 7;
        for (int b = 0; b < nb; b++) g_blk_aa[b0 + b] = a;
        cur += nb << 7;
    }
}

__global__ void __launch_bounds__(256) scatter_kernel(const int* __restrict__ aa)
{
    int i = blockIdx.x * blockDim.x + threadIdx.x;
    if (i >= M_TOK) return;
    int a = aa[i];
    int pos = g_base[a] + atomicAdd(&g_cnt[a], 1);
    g_perm[pos] = i;
}

// ---------------------------------------------------------------------------
// Frame construction
// ---------------------------------------------------------------------------
__global__ void __launch_bounds__(128) frame_kernel(
    const float* __restrict__ pos14, const void* __restrict__ maskp)
{
    __shared__ float sp[128 * CRD];
    const int tid  = threadIdx.x;
    const int base = blockIdx.x * 128;

    const size_t gbase = (size_t)base * CRD;
    #pragma unroll 4
    for (int i = tid; i < 128 * CRD; i += 128) sp[i] = pos14[gbase + i];
    __syncthreads();

    const float* p = &sp[tid * CRD];
    const int t = base + tid;

    const float cx = p[3], cy = p[4], cz = p[5];
    float v1x = p[6] - cx, v1y = p[7] - cy, v1z = p[8] - cz;
    float n1 = sqrtf(v1x*v1x + v1y*v1y + v1z*v1z) + EPSF;
    float e1x = v1x / n1, e1y = v1y / n1, e1z = v1z / n1;

    float v2x = p[0] - cx, v2y = p[1] - cy, v2z = p[2] - cz;
    float d = e1x*v2x + e1y*v2y + e1z*v2z;
    float u2x = v2x - d*e1x, u2y = v2y - d*e1y, u2z = v2z - d*e1z;
    float n2 = sqrtf(u2x*u2x + u2y*u2y + u2z*u2z) + EPSF;
    float e2x = u2x / n2, e2y = u2y / n2, e2z = u2z / n2;

    float e3x = e1y*e2z - e1z*e2y;
    float e3y = e1z*e2x - e1x*e2z;
    float e3z = e1x*e2y - e1y*e2x;

    const int mode = g_mask_mode;
    float r[CRD];
    #pragma unroll
    for (int a = 0; a < 14; a++) {
        float qx = p[a*3+0] - cx, qy = p[a*3+1] - cy, qz = p[a*3+2] - cz;
        bool mk = read_mask(maskp, mode, (size_t)t * 14 + a);
        r[a*3+0] = mk ? (e1x*qx + e1y*qy + e1z*qz) : 0.0f;
        r[a*3+1] = mk ? (e2x*qx + e2y*qy + e2z*qz) : 0.0f;
        r[a*3+2] = mk ? (e3x*qx + e3y*qy + e3z*qz) : 0.0f;
    }
    __syncthreads();
    #pragma unroll
    for (int i = 0; i < CRD; i++) sp[tid * CRD + i] = r[i];
    __syncthreads();
    #pragma unroll 4
    for (int i = tid; i < 128 * CRD; i += 128) g_crd[gbase + i] = sp[i];
}

// ---------------------------------------------------------------------------
// table[aa][j] = embed[aa] @ w1[882:1394, j] + b1[j]
// ---------------------------------------------------------------------------
__global__ void __launch_bounds__(256) embproj_kernel(
    const float* __restrict__ embed, const float* __restrict__ w1,
    const float* __restrict__ b1)
{
    __shared__ float se[FEATD];
    const int a = blockIdx.x;
    const int tid = threadIdx.x;
    for (int i = tid; i < FEATD; i += 256) se[i] = embed[a * FEATD + i];
    __syncthreads();

    const int j = tid * 4;
    float4 acc = *(const float4*)(b1 + j);
    const float* wp = w1 + (size_t)(NAA * CRD) * H1D + j;
    #pragma unroll 4
    for (int f = 0; f < FEATD; f++) {
        float e = se[f];
        float4 w = *(const float4*)(wp + (size_t)f * H1D);
        acc.x += e * w.x; acc.y += e * w.y; acc.z += e * w.z; acc.w += e * w.w;
    }
    *(float4*)(&g_table[a * H1D + j]) = acc;
}

// ---------------------------------------------------------------------------
// Pack fp32 weights [K][N] into k-pair half2 rows [K/2][N] (uint)
// ---------------------------------------------------------------------------
__global__ void __launch_bounds__(256) wpack_kernel(
    const float* __restrict__ w, unsigned* __restrict__ out, int K2, int N)
{
    int i = blockIdx.x * blockDim.x + threadIdx.x;
    if (i >= K2 * N) return;
    int k2 = i / N, n = i - k2 * N;
    out[i] = pack_h2(w[(size_t)(2*k2) * N + n], w[(size_t)(2*k2+1) * N + n]);
}

// ---------------------------------------------------------------------------
// Layer 1 as aa-grouped tf32 mma.sync GEMM (K=42 padded to 48), fp16 output.
// ---------------------------------------------------------------------------
#define L1_KP 48

__global__ void __launch_bounds__(256) layer1_gemm(const float* __restrict__ w1)
{
    extern __shared__ unsigned l1sm[];
    unsigned* s_crd = l1sm;                         // [128][52]
    unsigned* s_w   = l1sm + 128 * 52;              // [48][136]
    int*      s_tok = (int*)(l1sm + 128 * 52 + L1_KP * 136);
    float*    s_tab = (float*)(s_tok + 128);

    const int bm = blockIdx.y;
    const int a  = g_blk_aa[bm];
    if (a < 0) return;
    const int colbase = blockIdx.x * 128;

    const int tid  = threadIdx.x;
    const int wid  = tid >> 5;
    const int lane = tid & 31;
    const int gid  = lane >> 2;
    const int tig  = lane & 3;
    const int warpM = (wid >> 2) * 64;
    const int warpN = (wid & 3) * 32;

    for (int i = tid; i < 128 * 52; i += 256) s_crd[i] = 0;
    if (tid < 128) {
        s_tok[tid] = g_perm[bm * 128 + tid];
        s_tab[tid] = g_table[a * H1D + colbase + tid];
    }
    __syncthreads();

    for (int i = tid; i < 128 * CRD; i += 256) {
        int row = i / CRD, col = i - row * CRD;
        int t = s_tok[row];
        if (t >= 0) s_crd[row * 52 + col] = f2tf32(g_crd[(size_t)t * CRD + col]);
    }
    #pragma unroll
    for (int l = 0; l < 6; l++) {
        int s  = tid + l * 256;
        int kr = s >> 5;
        int nc = s & 31;
        float4 v = make_float4(0.f, 0.f, 0.f, 0.f);
        if (kr < CRD)
            v = *(const float4*)(w1 + (size_t)(a * CRD + kr) * H1D + colbase + nc * 4);
        s_w[kr * 136 + nc*4+0] = f2tf32(v.x);
        s_w[kr * 136 + nc*4+1] = f2tf32(v.y);
        s_w[kr * 136 + nc*4+2] = f2tf32(v.z);
        s_w[kr * 136 + nc*4+3] = f2tf32(v.w);
    }
    __syncthreads();

    float acc[4][4][4];
    #pragma unroll
    for (int i = 0; i < 4; i++)
        #pragma unroll
        for (int j = 0; j < 4; j++)
            #pragma unroll
            for (int c = 0; c < 4; c++) acc[i][j][c] = 0.0f;

    #pragma unroll
    for (int kt = 0; kt < L1_KP; kt += 8) {
        unsigned af[4][4], bf[4][2];
        #pragma unroll
        for (int mf = 0; mf < 4; mf++) {
            int r = warpM + mf * 16 + gid;
            af[mf][0] = s_crd[r * 52 + kt + tig];
            af[mf][1] = s_crd[(r + 8) * 52 + kt + tig];
            af[mf][2] = s_crd[r * 52 + kt + tig + 4];
            af[mf][3] = s_crd[(r + 8) * 52 + kt + tig + 4];
        }
        #pragma unroll
        for (int nf = 0; nf < 4; nf++) {
            int c = warpN + nf * 8 + gid;
            bf[nf][0] = s_w[(kt + tig) * 136 + c];
            bf[nf][1] = s_w[(kt + tig + 4) * 136 + c];
        }
        #pragma unroll
        for (int mf = 0; mf < 4; mf++)
            #pragma unroll
            for (int nf = 0; nf < 4; nf++)
                asm volatile(
                    "mma.sync.aligned.m16n8k8.row.col.f32.tf32.tf32.f32 "
                    "{%0,%1,%2,%3}, {%4,%5,%6,%7}, {%8,%9}, {%0,%1,%2,%3};"
                    : "+f"(acc[mf][nf][0]), "+f"(acc[mf][nf][1]),
                      "+f"(acc[mf][nf][2]), "+f"(acc[mf][nf][3])
                    : "r"(af[mf][0]), "r"(af[mf][1]), "r"(af[mf][2]), "r"(af[mf][3]),
                      "r"(bf[nf][0]), "r"(bf[nf][1]));
    }

    #pragma unroll
    for (int nf = 0; nf < 4; nf++) {
        int c = warpN + nf * 8 + 2 * tig;
        float bx = s_tab[c], by = s_tab[c + 1];
        #pragma unroll
        for (int mf = 0; mf < 4; mf++) {
            int r = warpM + mf * 16 + gid;
            int t0 = s_tok[r], t1 = s_tok[r + 8];
            if (t0 >= 0) {
                unsigned o = pack_h2(fmaxf(acc[mf][nf][0] + bx, 0.f),
                                     fmaxf(acc[mf][nf][1] + by, 0.f));
                *(unsigned*)(g_h1h + (size_t)t0 * H1D + colbase + c) = o;
            }
            if (t1 >= 0) {
                unsigned o = pack_h2(fmaxf(acc[mf][nf][2] + bx, 0.f),
                                     fmaxf(acc[mf][nf][3] + by, 0.f));
                *(unsigned*)(g_h1h + (size_t)t1 * H1D + colbase + c) = o;
            }
        }
    }
}

// ---------------------------------------------------------------------------
// fp16 GEMM with cp.async double-buffered staging.
// C = act(A[M,K] @ W[K,N] + b);  A fp16 row-major, Wp k-pair-packed [K/2][N].
// Tile 128x128x64, 256 thr, warp tile 64x32, mma.m16n8k16, fp32 accum.
// smem: Ah[2][128][36] uint (32 data k2 + 4 pad), Wh[2][32][136] uint.
// ---------------------------------------------------------------------------
#define GA_STRIDE 36
#define GW_STRIDE 136
#define GA_TILE  (128 * GA_STRIDE)
#define GW_TILE  (32 * GW_STRIDE)
#define G_SMEM   ((2 * (GA_TILE + GW_TILE)) * 4)

__global__ void __launch_bounds__(256) gemm_f16(
    const __half* __restrict__ A, const unsigned* __restrict__ Wp,
    const float* __restrict__ bias, void* __restrict__ Cout,
    int M, int K, int N, int relu, int out_half)
{
    extern __shared__ unsigned gsm[];
    unsigned* Ah = gsm;                       // [2][128][36]
    unsigned* Wh = gsm + 2 * GA_TILE;         // [2][32][136]

    const int tid  = threadIdx.x;
    const int wid  = tid >> 5;
    const int lane = tid & 31;
    const int gid  = lane >> 2;
    const int tig  = lane & 3;
    const int warpM = (wid >> 2) * 64;
    const int warpN = (wid & 3) * 32;
    const int row0 = blockIdx.y * 128;
    const int col0 = blockIdx.x * 128;

    const int K2 = K >> 1;

    // staging coords (fixed per thread): A 1024 slots = 4/thread, W same
    //  A slot s: r = s>>3 (0..127), kq = s&7   -> 8 halves = 16B
    //  W slot s: kr = s>>5 (0..31), nc = s&31  -> 4 uints  = 16B
    uint32_t aDst[2][4], wDst[2][4];
    const __half* aSrc[4];
    const unsigned* wSrc[4];
    #pragma unroll
    for (int l = 0; l < 4; l++) {
        int s = tid + l * 256;
        int r = s >> 3, kq = s & 7;
        aSrc[l] = A + (size_t)(row0 + r) * K + kq * 8;
        int skr = s >> 5, snc = s & 31;
        wSrc[l] = Wp + (size_t)skr * N + col0 + snc * 4;
        #pragma unroll
        for (int b = 0; b < 2; b++) {
            aDst[b][l] = smem_u32(&Ah[b * GA_TILE + r * GA_STRIDE + kq * 4]);
            wDst[b][l] = smem_u32(&Wh[b * GW_TILE + skr * GW_STRIDE + snc * 4]);
        }
    }

    #define STAGE(BUF, CH)                                                     \
        {                                                                      \
            _Pragma("unroll")                                                  \
            for (int l = 0; l < 4; l++)                                        \
                CP_ASYNC16(aDst[BUF][l], aSrc[l] + (size_t)(CH) * 64);         \
            _Pragma("unroll")                                                  \
            for (int l = 0; l < 4; l++)                                        \
                CP_ASYNC16(wDst[BUF][l], wSrc[l] + (size_t)(CH) * 32 * N);     \
            CP_COMMIT();                                                       \
        }

    float acc[4][4][4];
    #pragma unroll
    for (int i = 0; i < 4; i++)
        #pragma unroll
        for (int j = 0; j < 4; j++)
            #pragma unroll
            for (int c = 0; c < 4; c++) acc[i][j][c] = 0.0f;

    const int nk = K >> 6;                 // 64-k chunks
    STAGE(0, 0);

    for (int ch = 0; ch < nk; ch++) {
        const int buf = ch & 1;
        if (ch + 1 < nk) { STAGE(1 - buf, ch + 1); CP_WAIT(1); }
        else             { CP_WAIT(0); }
        __syncthreads();

        const unsigned* Ab = &Ah[buf * GA_TILE];
        const unsigned* Wb = &Wh[buf * GW_TILE];
        #pragma unroll
        for (int kt = 0; kt < 4; kt++) {
            const int kb = kt * 8;
            unsigned af[4][4], bf[4][2];
            #pragma unroll
            for (int mf = 0; mf < 4; mf++) {
                int r = warpM + mf * 16 + gid;
                af[mf][0] = Ab[r * GA_STRIDE + kb + tig];
                af[mf][1] = Ab[(r + 8) * GA_STRIDE + kb + tig];
                af[mf][2] = Ab[r * GA_STRIDE + kb + tig + 4];
                af[mf][3] = Ab[(r + 8) * GA_STRIDE + kb + tig + 4];
            }
            #pragma unroll
            for (int nf = 0; nf < 4; nf++) {
                int c = warpN + nf * 8 + gid;
                bf[nf][0] = Wb[(kb + tig) * GW_STRIDE + c];
                bf[nf][1] = Wb[(kb + tig + 4) * GW_STRIDE + c];
            }
            #pragma unroll
            for (int mf = 0; mf < 4; mf++)
                #pragma unroll
                for (int nf = 0; nf < 4; nf++)
                    asm volatile(
                        "mma.sync.aligned.m16n8k16.row.col.f32.f16.f16.f32 "
                        "{%0,%1,%2,%3}, {%4,%5,%6,%7}, {%8,%9}, {%0,%1,%2,%3};"
                        : "+f"(acc[mf][nf][0]), "+f"(acc[mf][nf][1]),
                          "+f"(acc[mf][nf][2]), "+f"(acc[mf][nf][3])
                        : "r"(af[mf][0]), "r"(af[mf][1]), "r"(af[mf][2]), "r"(af[mf][3]),
                          "r"(bf[nf][0]), "r"(bf[nf][1]));
        }
        __syncthreads();
    }

    // epilogue
    #pragma unroll
    for (int nf = 0; nf < 4; nf++) {
        int c = col0 + warpN + nf * 8 + 2 * tig;
        float bx = bias[c], by = bias[c + 1];
        #pragma unroll
        for (int mf = 0; mf < 4; mf++) {
            int r = row0 + warpM + mf * 16 + gid;
            float o0x = acc[mf][nf][0] + bx, o0y = acc[mf][nf][1] + by;
            float o1x = acc[mf][nf][2] + bx, o1y = acc[mf][nf][3] + by;
            if (relu) {
                o0x = fmaxf(o0x, 0.f); o0y = fmaxf(o0y, 0.f);
                o1x = fmaxf(o1x, 0.f); o1y = fmaxf(o1y, 0.f);
            }
            if (out_half) {
                __half* C = (__half*)Cout;
                *(unsigned*)(C + (size_t)r * N + c)       = pack_h2(o0x, o0y);
                *(unsigned*)(C + (size_t)(r + 8) * N + c) = pack_h2(o1x, o1y);
            } else {
                float* C = (float*)Cout;
                *(float2*)(C + (size_t)r * N + c)       = make_float2(o0x, o0y);
                *(float2*)(C + (size_t)(r + 8) * N + c) = make_float2(o1x, o1y);
            }
        }
    }
}

extern "C" void kernel_launch(void* const* d_in, const int* in_sizes, int n_in,
                              void* d_out, int out_size)
{
    const int*   aa    = (const int*)  d_in[0];
    const float* pos14 = (const float*)d_in[1];
    const void*  amask =               d_in[2];
    const float* embed = (const float*)d_in[3];
    const float* w1    = (const float*)d_in[4];
    const float* b1    = (const float*)d_in[5];
    const float* w2    = (const float*)d_in[6];
    const float* b2    = (const float*)d_in[7];
    const float* w3    = (const float*)d_in[8];
    const float* b3    = (const float*)d_in[9];
    const float* w4    = (const float*)d_in[10];
    const float* b4    = (const float*)d_in[11];

    __half *p_h1h, *p_h2h, *p_h3h;
    unsigned *p_w2p, *p_w3p, *p_w4p;
    cudaGetSymbolAddress((void**)&p_h1h, g_h1h);
    cudaGetSymbolAddress((void**)&p_h2h, g_h2h);
    cudaGetSymbolAddress((void**)&p_h3h, g_h3h);
    cudaGetSymbolAddress((void**)&p_w2p, g_w2p);
    cudaGetSymbolAddress((void**)&p_w3p, g_w3p);
    cudaGetSymbolAddress((void**)&p_w4p, g_w4p);

    const int l1sm = (128 * 52 + L1_KP * 136) * 4 + 128 * 4 + 128 * 4;
    cudaFuncSetAttribute(layer1_gemm, cudaFuncAttributeMaxDynamicSharedMemorySize,
                         l1sm);
    cudaFuncSetAttribute(gemm_f16, cudaFuncAttributeMaxDynamicSharedMemorySize,
                         G_SMEM);

    // sort tokens by aa
    sort_init_kernel<<<(MAXBLK * 128 + 255) / 256, 256>>>();
    hist_kernel<<<M_TOK / 1024, 256>>>(aa);
    scan_kernel<<<1, 32>>>();
    scatter_kernel<<<M_TOK / 256, 256>>>(aa);

    // geometry + aa-table + weight packing
    detect_mask_kernel<<<1, 256>>>((const unsigned int*)amask, 4096);
    frame_kernel<<<M_TOK / 128, 128>>>(pos14, amask);
    embproj_kernel<<<NAA, 256>>>(embed, w1, b1);
    wpack_kernel<<<(H1D/2  * FEATD + 255) / 256, 256>>>(w2, p_w2p, H1D/2,  FEATD);
    wpack_kernel<<<(FEATD/2* FEATD + 255) / 256, 256>>>(w3, p_w3p, FEATD/2, FEATD);
    wpack_kernel<<<(FEATD/2* FEATD + 255) / 256, 256>>>(w4, p_w4p, FEATD/2, FEATD);

    // layer 1 (grouped tf32 GEMM, fp16 out)
    {
        dim3 g(H1D / 128, MAXBLK);
        layer1_gemm<<<g, 256, l1sm>>>(w1);
    }

    // dense MLP (fp16 mma + cp.async double buffering)
    {
        dim3 blk(256);
        dim3 g2(FEATD / 128, M_TOK / 128);   // (4, 512)
        gemm_f16<<<g2, blk, G_SMEM>>>(p_h1h, p_w2p, b2, p_h2h, M_TOK, H1D,  FEATD, 1, 1);
        gemm_f16<<<g2, blk, G_SMEM>>>(p_h2h, p_w3p, b3, p_h3h, M_TOK, FEATD, FEATD, 1, 1);
        gemm_f16<<<g2, blk, G_SMEM>>>(p_h3h, p_w4p, b4, d_out, M_TOK, FEATD, FEATD, 0, 0);
    }
}

// round 7
// speedup vs baseline: 1.7855x; 1.0036x over previous
#include <cuda_runtime.h>
#include <cuda_fp16.h>
#include <cstdint>

// Problem constants (fixed shapes per reference)
#define M_TOK   65536          // N*L = 16*4096
#define FEATD   512
#define H1D     1024
#define NAA     21
#define CRD     42             // 14*3
#define EPSF    1e-6f
#define MAXBLK  533            // 65536/128 + 21 (padded 128-token groups)

// -------- static device scratch (no runtime allocation allowed) ----------
__device__ float    g_crd[(size_t)M_TOK * CRD];        // local coords
__device__ float    g_table[NAA * H1D];                // embed[aa]@w1[882:]+b1
__device__ __half   g_h1h[(size_t)M_TOK * H1D];        // 128 MB  (fp16 h1)
__device__ __half   g_h2h[(size_t)M_TOK * FEATD];      // 64 MB
__device__ __half   g_h3h[(size_t)M_TOK * FEATD];      // 64 MB
__device__ unsigned g_w2p[(size_t)(H1D/2)  * FEATD];   // k-pair packed half2
__device__ unsigned g_w3p[(size_t)(FEATD/2)* FEATD];
__device__ unsigned g_w4p[(size_t)(FEATD/2)* FEATD];
__device__ int      g_mask_mode;
// sorting scratch
__device__ int   g_hist[NAA];
__device__ int   g_cnt[NAA];
__device__ int   g_base[NAA];
__device__ int   g_blk_aa[MAXBLK];
__device__ int   g_perm[MAXBLK * 128];

// ---------------------------------------------------------------------------
__device__ __forceinline__ uint32_t smem_u32(const void* p)
{
    uint32_t a;
    asm("{ .reg .u64 t; cvta.to.shared.u64 t, %1; cvt.u32.u64 %0, t; }"
        : "=r"(a) : "l"(p));
    return a;
}

#define CP_ASYNC16(dst, src) \
    asm volatile("cp.async.cg.shared.global [%0], [%1], 16;" \
                 :: "r"(dst), "l"(src) : "memory")
#define CP_COMMIT()  asm volatile("cp.async.commit_group;" ::: "memory")
#define CP_WAIT(n)   asm volatile("cp.async.wait_group %0;" :: "n"(n) : "memory")

__device__ __forceinline__ unsigned f2tf32(float x)
{
    float r;
    asm("cvt.rna.tf32.f32 %0, %1;" : "=f"(r) : "f"(x));
    return __float_as_uint(r);
}

__device__ __forceinline__ unsigned pack_h2(float a, float b)
{
    __half2 h = __floats2half2_rn(a, b);
    return *(unsigned*)&h;
}

// ---------------------------------------------------------------------------
// Mask dtype sniffer
// ---------------------------------------------------------------------------
__global__ void detect_mask_kernel(const unsigned int* __restrict__ m, int n_words)
{
    __shared__ int sawFloat, sawBig;
    int tid = threadIdx.x;
    if (tid == 0) { sawFloat = 0; sawBig = 0; }
    __syncthreads();
    for (int i = tid; i < n_words; i += blockDim.x) {
        unsigned v = m[i];
        if (v == 0x3F800000u)      sawFloat = 1;
        else if (v > 1u)           sawBig   = 1;
    }
    __syncthreads();
    if (tid == 0) g_mask_mode = sawFloat ? 1 : (sawBig ? 2 : 0);
}

__device__ __forceinline__ bool read_mask(const void* m, int mode, size_t i)
{
    if (mode == 0) return ((const int*)m)[i] != 0;
    if (mode == 1) return ((const float*)m)[i] != 0.0f;
    return ((const unsigned char*)m)[i] != 0;
}

// ---------------------------------------------------------------------------
// Counting sort of tokens by aa
// ---------------------------------------------------------------------------
__global__ void sort_init_kernel()
{
    int i = blockIdx.x * blockDim.x + threadIdx.x;
    if (i < NAA) { g_hist[i] = 0; g_cnt[i] = 0; }
    if (i < MAXBLK) g_blk_aa[i] = -1;
    if (i < MAXBLK * 128) g_perm[i] = -1;
}

__global__ void __launch_bounds__(256) hist_kernel(const int* __restrict__ aa)
{
    __shared__ int h[NAA];
    int tid = threadIdx.x;
    if (tid < NAA) h[tid] = 0;
    __syncthreads();
    int base = blockIdx.x * 1024;
    for (int j = tid; j < 1024; j += 256) atomicAdd(&h[aa[base + j]], 1);
    __syncthreads();
    if (tid < NAA) atomicAdd(&g_hist[tid], h[tid]);
}

__global__ void scan_kernel()
{
    if (threadIdx.x != 0) return;
    int cur = 0;
    for (int a = 0; a < NAA; a++) {
        g_base[a] = cur;
        int nb = (g_hist[a] + 127) >> 7;
        int b0 = cur >> 7;
        for (int b = 0; b < nb; b++) g_blk_aa[b0 + b] = a;
        cur += nb << 7;
    }
}

__global__ void __launch_bounds__(256) scatter_kernel(const int* __restrict__ aa)
{
    int i = blockIdx.x * blockDim.x + threadIdx.x;
    if (i >= M_TOK) return;
    int a = aa[i];
    int pos = g_base[a] + atomicAdd(&g_cnt[a], 1);
    g_perm[pos] = i;
}

// ---------------------------------------------------------------------------
// Frame construction
// ---------------------------------------------------------------------------
__global__ void __launch_bounds__(128) frame_kernel(
    const float* __restrict__ pos14, const void* __restrict__ maskp)
{
    __shared__ float sp[128 * CRD];
    const int tid  = threadIdx.x;
    const int base = blockIdx.x * 128;

    const size_t gbase = (size_t)base * CRD;
    #pragma unroll 4
    for (int i = tid; i < 128 * CRD; i += 128) sp[i] = pos14[gbase + i];
    __syncthreads();

    const float* p = &sp[tid * CRD];
    const int t = base + tid;

    const float cx = p[3], cy = p[4], cz = p[5];
    float v1x = p[6] - cx, v1y = p[7] - cy, v1z = p[8] - cz;
    float n1 = sqrtf(v1x*v1x + v1y*v1y + v1z*v1z) + EPSF;
    float e1x = v1x / n1, e1y = v1y / n1, e1z = v1z / n1;

    float v2x = p[0] - cx, v2y = p[1] - cy, v2z = p[2] - cz;
    float d = e1x*v2x + e1y*v2y + e1z*v2z;
    float u2x = v2x - d*e1x, u2y = v2y - d*e1y, u2z = v2z - d*e1z;
    float n2 = sqrtf(u2x*u2x + u2y*u2y + u2z*u2z) + EPSF;
    float e2x = u2x / n2, e2y = u2y / n2, e2z = u2z / n2;

    float e3x = e1y*e2z - e1z*e2y;
    float e3y = e1z*e2x - e1x*e2z;
    float e3z = e1x*e2y - e1y*e2x;

    const int mode = g_mask_mode;
    float r[CRD];
    #pragma unroll
    for (int a = 0; a < 14; a++) {
        float qx = p[a*3+0] - cx, qy = p[a*3+1] - cy, qz = p[a*3+2] - cz;
        bool mk = read_mask(maskp, mode, (size_t)t * 14 + a);
        r[a*3+0] = mk ? (e1x*qx + e1y*qy + e1z*qz) : 0.0f;
        r[a*3+1] = mk ? (e2x*qx + e2y*qy + e2z*qz) : 0.0f;
        r[a*3+2] = mk ? (e3x*qx + e3y*qy + e3z*qz) : 0.0f;
    }
    __syncthreads();
    #pragma unroll
    for (int i = 0; i < CRD; i++) sp[tid * CRD + i] = r[i];
    __syncthreads();
    #pragma unroll 4
    for (int i = tid; i < 128 * CRD; i += 128) g_crd[gbase + i] = sp[i];
}

// ---------------------------------------------------------------------------
// table[aa][j] = embed[aa] @ w1[882:1394, j] + b1[j]
// ---------------------------------------------------------------------------
__global__ void __launch_bounds__(256) embproj_kernel(
    const float* __restrict__ embed, const float* __restrict__ w1,
    const float* __restrict__ b1)
{
    __shared__ float se[FEATD];
    const int a = blockIdx.x;
    const int tid = threadIdx.x;
    for (int i = tid; i < FEATD; i += 256) se[i] = embed[a * FEATD + i];
    __syncthreads();

    const int j = tid * 4;
    float4 acc = *(const float4*)(b1 + j);
    const float* wp = w1 + (size_t)(NAA * CRD) * H1D + j;
    #pragma unroll 4
    for (int f = 0; f < FEATD; f++) {
        float e = se[f];
        float4 w = *(const float4*)(wp + (size_t)f * H1D);
        acc.x += e * w.x; acc.y += e * w.y; acc.z += e * w.z; acc.w += e * w.w;
    }
    *(float4*)(&g_table[a * H1D + j]) = acc;
}

// ---------------------------------------------------------------------------
// Pack fp32 weights [K][N] into k-pair half2 rows [K/2][N] (uint)
// ---------------------------------------------------------------------------
__global__ void __launch_bounds__(256) wpack_kernel(
    const float* __restrict__ w, unsigned* __restrict__ out, int K2, int N)
{
    int i = blockIdx.x * blockDim.x + threadIdx.x;
    if (i >= K2 * N) return;
    int k2 = i / N, n = i - k2 * N;
    out[i] = pack_h2(w[(size_t)(2*k2) * N + n], w[(size_t)(2*k2+1) * N + n]);
}

// ---------------------------------------------------------------------------
// Layer 1 as aa-grouped tf32 mma.sync GEMM (K=42 padded to 48), fp16 output.
// ---------------------------------------------------------------------------
#define L1_KP 48

__global__ void __launch_bounds__(256) layer1_gemm(const float* __restrict__ w1)
{
    extern __shared__ unsigned l1sm[];
    unsigned* s_crd = l1sm;                         // [128][52]
    unsigned* s_w   = l1sm + 128 * 52;              // [48][136]
    int*      s_tok = (int*)(l1sm + 128 * 52 + L1_KP * 136);
    float*    s_tab = (float*)(s_tok + 128);

    const int bm = blockIdx.y;
    const int a  = g_blk_aa[bm];
    if (a < 0) return;
    const int colbase = blockIdx.x * 128;

    const int tid  = threadIdx.x;
    const int wid  = tid >> 5;
    const int lane = tid & 31;
    const int gid  = lane >> 2;
    const int tig  = lane & 3;
    const int warpM = (wid >> 2) * 64;
    const int warpN = (wid & 3) * 32;

    for (int i = tid; i < 128 * 52; i += 256) s_crd[i] = 0;
    if (tid < 128) {
        s_tok[tid] = g_perm[bm * 128 + tid];
        s_tab[tid] = g_table[a * H1D + colbase + tid];
    }
    __syncthreads();

    for (int i = tid; i < 128 * CRD; i += 256) {
        int row = i / CRD, col = i - row * CRD;
        int t = s_tok[row];
        if (t >= 0) s_crd[row * 52 + col] = f2tf32(g_crd[(size_t)t * CRD + col]);
    }
    #pragma unroll
    for (int l = 0; l < 6; l++) {
        int s  = tid + l * 256;
        int kr = s >> 5;
        int nc = s & 31;
        float4 v = make_float4(0.f, 0.f, 0.f, 0.f);
        if (kr < CRD)
            v = *(const float4*)(w1 + (size_t)(a * CRD + kr) * H1D + colbase + nc * 4);
        s_w[kr * 136 + nc*4+0] = f2tf32(v.x);
        s_w[kr * 136 + nc*4+1] = f2tf32(v.y);
        s_w[kr * 136 + nc*4+2] = f2tf32(v.z);
        s_w[kr * 136 + nc*4+3] = f2tf32(v.w);
    }
    __syncthreads();

    float acc[4][4][4];
    #pragma unroll
    for (int i = 0; i < 4; i++)
        #pragma unroll
        for (int j = 0; j < 4; j++)
            #pragma unroll
            for (int c = 0; c < 4; c++) acc[i][j][c] = 0.0f;

    #pragma unroll
    for (int kt = 0; kt < L1_KP; kt += 8) {
        unsigned af[4][4], bf[4][2];
        #pragma unroll
        for (int mf = 0; mf < 4; mf++) {
            int r = warpM + mf * 16 + gid;
            af[mf][0] = s_crd[r * 52 + kt + tig];
            af[mf][1] = s_crd[(r + 8) * 52 + kt + tig];
            af[mf][2] = s_crd[r * 52 + kt + tig + 4];
            af[mf][3] = s_crd[(r + 8) * 52 + kt + tig + 4];
        }
        #pragma unroll
        for (int nf = 0; nf < 4; nf++) {
            int c = warpN + nf * 8 + gid;
            bf[nf][0] = s_w[(kt + tig) * 136 + c];
            bf[nf][1] = s_w[(kt + tig + 4) * 136 + c];
        }
        #pragma unroll
        for (int mf = 0; mf < 4; mf++)
            #pragma unroll
            for (int nf = 0; nf < 4; nf++)
                asm volatile(
                    "mma.sync.aligned.m16n8k8.row.col.f32.tf32.tf32.f32 "
                    "{%0,%1,%2,%3}, {%4,%5,%6,%7}, {%8,%9}, {%0,%1,%2,%3};"
                    : "+f"(acc[mf][nf][0]), "+f"(acc[mf][nf][1]),
                      "+f"(acc[mf][nf][2]), "+f"(acc[mf][nf][3])
                    : "r"(af[mf][0]), "r"(af[mf][1]), "r"(af[mf][2]), "r"(af[mf][3]),
                      "r"(bf[nf][0]), "r"(bf[nf][1]));
    }

    #pragma unroll
    for (int nf = 0; nf < 4; nf++) {
        int c = warpN + nf * 8 + 2 * tig;
        float bx = s_tab[c], by = s_tab[c + 1];
        #pragma unroll
        for (int mf = 0; mf < 4; mf++) {
            int r = warpM + mf * 16 + gid;
            int t0 = s_tok[r], t1 = s_tok[r + 8];
            if (t0 >= 0) {
                unsigned o = pack_h2(fmaxf(acc[mf][nf][0] + bx, 0.f),
                                     fmaxf(acc[mf][nf][1] + by, 0.f));
                *(unsigned*)(g_h1h + (size_t)t0 * H1D + colbase + c) = o;
            }
            if (t1 >= 0) {
                unsigned o = pack_h2(fmaxf(acc[mf][nf][2] + bx, 0.f),
                                     fmaxf(acc[mf][nf][3] + by, 0.f));
                *(unsigned*)(g_h1h + (size_t)t1 * H1D + colbase + c) = o;
            }
        }
    }
}

// ---------------------------------------------------------------------------
// fp16 GEMM, cp.async double-buffered, block tile 128x256x64, warp tile 64x64.
// C = act(A[M,K] @ W[K,N] + b);  A fp16 row-major, Wp k-pair-packed [K/2][N].
// 256 thr (8 warps as 2x4), mma.m16n8k16, fp32 accum.  N must be 512 here.
// smem: Ah[2][128][36] uint, Wh[2][32][264] uint  (~102 KB dynamic)
// ---------------------------------------------------------------------------
#define GA_STRIDE 36
#define GW_STRIDE 264
#define GA_TILE  (128 * GA_STRIDE)
#define GW_TILE  (32 * GW_STRIDE)
#define G_SMEM   ((2 * (GA_TILE + GW_TILE)) * 4)

__global__ void __launch_bounds__(256, 1) gemm_f16(
    const __half* __restrict__ A, const unsigned* __restrict__ Wp,
    const float* __restrict__ bias, void* __restrict__ Cout,
    int M, int K, int N, int relu, int out_half)
{
    extern __shared__ unsigned gsm[];
    unsigned* Ah = gsm;                       // [2][128][36]
    unsigned* Wh = gsm + 2 * GA_TILE;         // [2][32][264]

    const int tid  = threadIdx.x;
    const int wid  = tid >> 5;
    const int lane = tid & 31;
    const int gid  = lane >> 2;
    const int tig  = lane & 3;
    const int warpM = (wid >> 2) * 64;        // 0 or 64
    const int warpN = (wid & 3) * 64;         // 0,64,128,192
    const int row0 = blockIdx.y * 128;
    const int col0 = blockIdx.x * 256;

    // staging coords: A 1024 slots = 4/thread; W 2048 slots = 8/thread
    uint32_t aDst[2][4], wDst[2][8];
    const __half* aSrc[4];
    const unsigned* wSrc[8];
    #pragma unroll
    for (int l = 0; l < 4; l++) {
        int s = tid + l * 256;
        int r = s >> 3, kq = s & 7;
        aSrc[l] = A + (size_t)(row0 + r) * K + kq * 8;
        #pragma unroll
        for (int b = 0; b < 2; b++)
            aDst[b][l] = smem_u32(&Ah[b * GA_TILE + r * GA_STRIDE + kq * 4]);
    }
    #pragma unroll
    for (int l = 0; l < 8; l++) {
        int s = tid + l * 256;
        int kr = s >> 6, nc = s & 63;
        wSrc[l] = Wp + (size_t)kr * N + col0 + nc * 4;
        #pragma unroll
        for (int b = 0; b < 2; b++)
            wDst[b][l] = smem_u32(&Wh[b * GW_TILE + kr * GW_STRIDE + nc * 4]);
    }

    #define STAGE(BUF, CH)                                                     \
        {                                                                      \
            _Pragma("unroll")                                                  \
            for (int l = 0; l < 4; l++)                                        \
                CP_ASYNC16(aDst[BUF][l], aSrc[l] + (size_t)(CH) * 64);         \
            _Pragma("unroll")                                                  \
            for (int l = 0; l < 8; l++)                                        \
                CP_ASYNC16(wDst[BUF][l], wSrc[l] + (size_t)(CH) * 32 * N);     \
            CP_COMMIT();                                                       \
        }

    float acc[4][8][4];                       // [mfrag 16-rows][nfrag 8-cols][c]
    #pragma unroll
    for (int i = 0; i < 4; i++)
        #pragma unroll
        for (int j = 0; j < 8; j++)
            #pragma unroll
            for (int c = 0; c < 4; c++) acc[i][j][c] = 0.0f;

    const int nk = K >> 6;                    // 64-k chunks
    STAGE(0, 0);

    for (int ch = 0; ch < nk; ch++) {
        const int buf = ch & 1;
        if (ch + 1 < nk) { STAGE(1 - buf, ch + 1); CP_WAIT(1); }
        else             { CP_WAIT(0); }
        __syncthreads();

        const unsigned* Ab = &Ah[buf * GA_TILE];
        const unsigned* Wb = &Wh[buf * GW_TILE];
        #pragma unroll
        for (int kt = 0; kt < 4; kt++) {
            const int kb = kt * 8;
            unsigned af[4][4];
            #pragma unroll
            for (int mf = 0; mf < 4; mf++) {
                int r = warpM + mf * 16 + gid;
                af[mf][0] = Ab[r * GA_STRIDE + kb + tig];
                af[mf][1] = Ab[(r + 8) * GA_STRIDE + kb + tig];
                af[mf][2] = Ab[r * GA_STRIDE + kb + tig + 4];
                af[mf][3] = Ab[(r + 8) * GA_STRIDE + kb + tig + 4];
            }
            #pragma unroll
            for (int nf = 0; nf < 8; nf++) {
                int c = warpN + nf * 8 + gid;
                unsigned b0 = Wb[(kb + tig) * GW_STRIDE + c];
                unsigned b1 = Wb[(kb + tig + 4) * GW_STRIDE + c];
                #pragma unroll
                for (int mf = 0; mf < 4; mf++)
                    asm volatile(
                        "mma.sync.aligned.m16n8k16.row.col.f32.f16.f16.f32 "
                        "{%0,%1,%2,%3}, {%4,%5,%6,%7}, {%8,%9}, {%0,%1,%2,%3};"
                        : "+f"(acc[mf][nf][0]), "+f"(acc[mf][nf][1]),
                          "+f"(acc[mf][nf][2]), "+f"(acc[mf][nf][3])
                        : "r"(af[mf][0]), "r"(af[mf][1]), "r"(af[mf][2]), "r"(af[mf][3]),
                          "r"(b0), "r"(b1));
            }
        }
        __syncthreads();
    }

    // epilogue
    #pragma unroll
    for (int nf = 0; nf < 8; nf++) {
        int c = col0 + warpN + nf * 8 + 2 * tig;
        float bx = bias[c], by = bias[c + 1];
        #pragma unroll
        for (int mf = 0; mf < 4; mf++) {
            int r = row0 + warpM + mf * 16 + gid;
            float o0x = acc[mf][nf][0] + bx, o0y = acc[mf][nf][1] + by;
            float o1x = acc[mf][nf][2] + bx, o1y = acc[mf][nf][3] + by;
            if (relu) {
                o0x = fmaxf(o0x, 0.f); o0y = fmaxf(o0y, 0.f);
                o1x = fmaxf(o1x, 0.f); o1y = fmaxf(o1y, 0.f);
            }
            if (out_half) {
                __half* C = (__half*)Cout;
                *(unsigned*)(C + (size_t)r * N + c)       = pack_h2(o0x, o0y);
                *(unsigned*)(C + (size_t)(r + 8) * N + c) = pack_h2(o1x, o1y);
            } else {
                float* C = (float*)Cout;
                *(float2*)(C + (size_t)r * N + c)       = make_float2(o0x, o0y);
                *(float2*)(C + (size_t)(r + 8) * N + c) = make_float2(o1x, o1y);
            }
        }
    }
}

extern "C" void kernel_launch(void* const* d_in, const int* in_sizes, int n_in,
                              void* d_out, int out_size)
{
    const int*   aa    = (const int*)  d_in[0];
    const float* pos14 = (const float*)d_in[1];
    const void*  amask =               d_in[2];
    const float* embed = (const float*)d_in[3];
    const float* w1    = (const float*)d_in[4];
    const float* b1    = (const float*)d_in[5];
    const float* w2    = (const float*)d_in[6];
    const float* b2    = (const float*)d_in[7];
    const float* w3    = (const float*)d_in[8];
    const float* b3    = (const float*)d_in[9];
    const float* w4    = (const float*)d_in[10];
    const float* b4    = (const float*)d_in[11];

    __half *p_h1h, *p_h2h, *p_h3h;
    unsigned *p_w2p, *p_w3p, *p_w4p;
    cudaGetSymbolAddress((void**)&p_h1h, g_h1h);
    cudaGetSymbolAddress((void**)&p_h2h, g_h2h);
    cudaGetSymbolAddress((void**)&p_h3h, g_h3h);
    cudaGetSymbolAddress((void**)&p_w2p, g_w2p);
    cudaGetSymbolAddress((void**)&p_w3p, g_w3p);
    cudaGetSymbolAddress((void**)&p_w4p, g_w4p);

    const int l1sm = (128 * 52 + L1_KP * 136) * 4 + 128 * 4 + 128 * 4;
    cudaFuncSetAttribute(layer1_gemm, cudaFuncAttributeMaxDynamicSharedMemorySize,
                         l1sm);
    cudaFuncSetAttribute(gemm_f16, cudaFuncAttributeMaxDynamicSharedMemorySize,
                         G_SMEM);

    // sort tokens by aa
    sort_init_kernel<<<(MAXBLK * 128 + 255) / 256, 256>>>();
    hist_kernel<<<M_TOK / 1024, 256>>>(aa);
    scan_kernel<<<1, 32>>>();
    scatter_kernel<<<M_TOK / 256, 256>>>(aa);

    // geometry + aa-table + weight packing
    detect_mask_kernel<<<1, 256>>>((const unsigned int*)amask, 4096);
    frame_kernel<<<M_TOK / 128, 128>>>(pos14, amask);
    embproj_kernel<<<NAA, 256>>>(embed, w1, b1);
    wpack_kernel<<<(H1D/2  * FEATD + 255) / 256, 256>>>(w2, p_w2p, H1D/2,  FEATD);
    wpack_kernel<<<(FEATD/2* FEATD + 255) / 256, 256>>>(w3, p_w3p, FEATD/2, FEATD);
    wpack_kernel<<<(FEATD/2* FEATD + 255) / 256, 256>>>(w4, p_w4p, FEATD/2, FEATD);

    // layer 1 (grouped tf32 GEMM, fp16 out)
    {
        dim3 g(H1D / 128, MAXBLK);
        layer1_gemm<<<g, 256, l1sm>>>(w1);
    }

    // dense MLP (fp16 mma + cp.async, 128x256 block tile)
    {
        dim3 blk(256);
        dim3 g2(FEATD / 256, M_TOK / 128);   // (2, 512)
        gemm_f16<<<g2, blk, G_SMEM>>>(p_h1h, p_w2p, b2, p_h2h, M_TOK, H1D,  FEATD, 1, 1);
        gemm_f16<<<g2, blk, G_SMEM>>>(p_h2h, p_w3p, b3, p_h3h, M_TOK, FEATD, FEATD, 1, 1);
        gemm_f16<<<g2, blk, G_SMEM>>>(p_h3h, p_w4p, b4, d_out, M_TOK, FEATD, FEATD, 0, 0);
    }
}